// round 13
// baseline (speedup 1.0000x reference)
#include <cuda_runtime.h>
#include <cuda_fp16.h>
#include <stdint.h>

// Problem constants (fixed for GCN_69097433858735)
#define NN 100000
#define EE 3200000
#define FIN 128
#define HH 16
#define CC 2
#define T 256

// Static scratch (zero-initialized at load; g_cnt zero-invariant restored by k_final)
__device__ int   g_cnt [NN];                      // in-degree (edges only)
__device__ float g_dinv[NN];                      // rsqrt(deg+1)
__device__ __align__(16) float  g_h   [NN * HH];  // x@W1 (unscaled)
__device__ __align__(16) __half g_hsh [NN * HH];  // h * dinv[n]  (fp16 scatter payload)
__device__ __align__(16) float  g_acc1[NN * HH];  // seeded with self-loop di*h
__device__ __align__(16) float  g_gs  [NN * CC];  // (relu_out @ W2) * dinv[n]
__device__ __align__(16) float  g_acc2[NN * CC];

__device__ __forceinline__ unsigned h2_bits(__half2 h) {
    return *reinterpret_cast<unsigned*>(&h);
}

// 1) FUSED (sequential split): blocks [0, gemm_blocks) compute h = x@W1
//    (unscaled, 4 threads/row); blocks [gemm_blocks, ...) count in-degrees
//    (4 edges/thread). Count blocks backfill as the gemm wave drains.
__global__ __launch_bounds__(T) void k_fused(const float* __restrict__ x,
                                             const float* __restrict__ W1,
                                             const int* __restrict__ ei,
                                             int n, int e, int gemm_blocks) {
    if ((int)blockIdx.x >= gemm_blocks) {
        // ---- degree count part: int4-vectorized over the dst half ----
        int base = ((blockIdx.x - gemm_blocks) * T + threadIdx.x) * 4;
        if (base >= e) return;
        const int* dstp = ei + e;
        if (base + 3 < e) {
            int4 d4 = *(const int4*)(dstp + base);
            int a = d4.x, b = d4.y, c = d4.z, d = d4.w;
            if ((unsigned)a >= NN) a = 0;
            if ((unsigned)b >= NN) b = 0;
            if ((unsigned)c >= NN) c = 0;
            if ((unsigned)d >= NN) d = 0;
            atomicAdd(&g_cnt[a], 1);
            atomicAdd(&g_cnt[b], 1);
            atomicAdd(&g_cnt[c], 1);
            atomicAdd(&g_cnt[d], 1);
        } else {
            for (int i = base; i < e; i++) {
                int d = dstp[i];
                if ((unsigned)d >= NN) d = 0;
                atomicAdd(&g_cnt[d], 1);
            }
        }
        return;
    }
    // ---- gemm part: 4 threads per row, each covers 32 K-elements ----
    __shared__ float sW1[FIN * HH];  // 8 KB
    for (int i = threadIdx.x; i < FIN * HH; i += T)
        sW1[i] = W1[i];
    __syncthreads();

    int t   = blockIdx.x * T + threadIdx.x;
    int row = t >> 2;
    int qt  = t & 3;                 // K-quarter
    if (row >= n) return;

    float acc[HH];
#pragma unroll
    for (int j = 0; j < HH; j++) acc[j] = 0.0f;

    const float4* xr = (const float4*)(x + (long long)row * FIN) + qt * 8;
    const float*  w  = sW1 + qt * 32 * HH;
#pragma unroll
    for (int k4 = 0; k4 < 8; k4++) {
        float4 xv = __ldcs(&xr[k4]);   // streaming: read-once data
        int k = k4 * 4;
#pragma unroll
        for (int j = 0; j < HH; j++) {
            acc[j] += xv.x * w[(k + 0) * HH + j];
            acc[j] += xv.y * w[(k + 1) * HH + j];
            acc[j] += xv.z * w[(k + 2) * HH + j];
            acc[j] += xv.w * w[(k + 3) * HH + j];
        }
    }
    // combine the 4 K-quarters (partner lanes differ in bits 0-1)
#pragma unroll
    for (int j = 0; j < HH; j++) {
        acc[j] += __shfl_xor_sync(0xffffffffu, acc[j], 1);
        acc[j] += __shfl_xor_sync(0xffffffffu, acc[j], 2);
    }
    ((float4*)(g_h + (long long)row * HH))[qt] =
        make_float4(acc[qt * 4 + 0], acc[qt * 4 + 1], acc[qt * 4 + 2], acc[qt * 4 + 3]);
}

// 2) scale: dinv = rsqrt(cnt+1); hsh = fp16(h*dinv); acc1 seeded = di*h
//    (the self-loop message), so fin1 needs neither a zero nor g_h.
__global__ __launch_bounds__(T) void k_scale(int n) {
    int t   = blockIdx.x * T + threadIdx.x;
    int row = t >> 1;
    int hf  = t & 1;
    if (row >= n) return;
    float di = rsqrtf((float)(g_cnt[row] + 1));
    if (hf == 0) g_dinv[row] = di;
    const float4* h4 = (const float4*)(g_h + (long long)row * HH) + hf * 2;
    float4 a = h4[0];
    float4 b = h4[1];
    a.x *= di; a.y *= di; a.z *= di; a.w *= di;
    b.x *= di; b.y *= di; b.z *= di; b.w *= di;
    uint4 packed;
    packed.x = h2_bits(__floats2half2_rn(a.x, a.y));
    packed.y = h2_bits(__floats2half2_rn(a.z, a.w));
    packed.z = h2_bits(__floats2half2_rn(b.x, b.y));
    packed.w = h2_bits(__floats2half2_rn(b.z, b.w));
    *((uint4*)(g_hsh + (long long)row * HH) + hf) = packed;
    float4* a4 = (float4*)(g_acc1 + (long long)row * HH) + hf * 2;
    a4[0] = a;   // self-loop seed (fp32, exact)
    a4[1] = b;
}

// 3) scatter layer 1: acc1[dst] += hs[src] — 4 threads per edge, fp16 gather,
//    fp32 float4 RED (one gather line + one RED line per edge).
__global__ __launch_bounds__(T) void k_scatter1(const int* __restrict__ ei, int e) {
    int gt    = blockIdx.x * T + threadIdx.x;
    int lane  = threadIdx.x & 31;
    int wbase = (gt >> 5) * 8;          // first edge of this warp
    int k = lane >> 2;                  // edge slot within warp (0..7)
    int q = lane & 3;                   // quarter of the 16-feature row

    // coalesced index loads: lanes 0-7 load 8 src, lanes 8-15 load 8 dst
    int idx = wbase + (lane & 7);
    int tmp = 0;
    if (lane < 16 && idx < e)
        tmp = (lane < 8) ? ei[idx] : ei[e + idx];
    int s = __shfl_sync(0xffffffffu, tmp, k);
    int d = __shfl_sync(0xffffffffu, tmp, 8 + k);

    int eb = wbase + k;
    if (eb >= e) return;
    if ((unsigned)s >= NN) s = 0;
    if ((unsigned)d >= NN) d = 0;

    uint2 raw = __ldg((const uint2*)(g_hsh + (long long)s * HH) + q);
    __half2 h0 = *(__half2*)&raw.x;
    __half2 h1 = *(__half2*)&raw.y;
    float2 f0 = __half22float2(h0);
    float2 f1 = __half22float2(h1);
    float4 v = make_float4(f0.x, f0.y, f1.x, f1.y);
    atomicAdd((float4*)(g_acc1 + (long long)d * HH) + q, v);
}

// 4) layer-1 epilogue + GEMM2: out1 = relu(di*acc1 + b1)  (acc1 includes self-loop);
//    gs = (out1 @ W2) * di; zero acc2
__global__ __launch_bounds__(T) void k_fin1_gemm2(const float* __restrict__ b1,
                                                  const float* __restrict__ W2,
                                                  int n) {
    __shared__ float sW2[HH * CC];
    __shared__ float sb1[HH];
    for (int i = threadIdx.x; i < HH * CC; i += T) sW2[i] = W2[i];
    for (int i = threadIdx.x; i < HH; i += T) sb1[i] = b1[i];
    __syncthreads();

    int row = blockIdx.x * T + threadIdx.x;
    if (row >= n) return;
    float di = g_dinv[row];

    const float4* ac4 = (const float4*)(g_acc1 + (long long)row * HH);
    float gc0 = 0.f, gc1 = 0.f;
#pragma unroll
    for (int q = 0; q < HH / 4; q++) {
        float4 a = ac4[q];
        float o0 = fmaxf(di * a.x + sb1[q * 4 + 0], 0.f);
        float o1 = fmaxf(di * a.y + sb1[q * 4 + 1], 0.f);
        float o2 = fmaxf(di * a.z + sb1[q * 4 + 2], 0.f);
        float o3 = fmaxf(di * a.w + sb1[q * 4 + 3], 0.f);
        gc0 += o0 * sW2[(q * 4 + 0) * CC + 0] + o1 * sW2[(q * 4 + 1) * CC + 0]
             + o2 * sW2[(q * 4 + 2) * CC + 0] + o3 * sW2[(q * 4 + 3) * CC + 0];
        gc1 += o0 * sW2[(q * 4 + 0) * CC + 1] + o1 * sW2[(q * 4 + 1) * CC + 1]
             + o2 * sW2[(q * 4 + 2) * CC + 1] + o3 * sW2[(q * 4 + 3) * CC + 1];
    }
    *(float2*)(g_gs   + (long long)row * CC) = make_float2(gc0 * di, gc1 * di);
    *(float2*)(g_acc2 + (long long)row * CC) = make_float2(gc0 * di, gc1 * di); // self-loop seed
}

// 5) scatter layer 2: acc2[dst] += gs[src]  (float2 atomicAdd)
__global__ __launch_bounds__(T) void k_scatter2(const int* __restrict__ ei, int e) {
    int i = blockIdx.x * T + threadIdx.x;
    if (i >= e) return;
    int s = ei[i];
    int d = ei[e + i];
    if ((unsigned)s >= NN) s = 0;
    if ((unsigned)d >= NN) d = 0;
    float2 v = __ldg((const float2*)(g_gs + (long long)s * CC));
    atomicAdd((float2*)(g_acc2 + (long long)d * CC), v);
}

// 6) final: out = dinv*acc2 + b2 (acc2 includes self-loop); restore g_cnt zeros
__global__ void k_final(const float* __restrict__ b2, float* __restrict__ out, int n) {
    int row = blockIdx.x * blockDim.x + threadIdx.x;
    if (row >= n) return;
    float di = g_dinv[row];
    float2 a = *((const float2*)(g_acc2 + (long long)row * CC));
    float2 o;
    o.x = di * a.x + b2[0];
    o.y = di * a.y + b2[1];
    *((float2*)(out + (long long)row * CC)) = o;
    g_cnt[row] = 0;   // ready for next graph replay
}

extern "C" void kernel_launch(void* const* d_in, const int* in_sizes, int n_in,
                              void* d_out, int out_size) {
    const float* x  = (const float*)d_in[0];
    const int*   ei = (const int*)d_in[1];    // int32 (JAX x64 disabled)
    const float* W1 = (const float*)d_in[2];
    const float* b1 = (const float*)d_in[3];
    const float* W2 = (const float*)d_in[4];
    const float* b2 = (const float*)d_in[5];
    float* out = (float*)d_out;

    int n = in_sizes[0] / FIN;     // 100000
    int e = in_sizes[1] / 2;       // 3200000

    int gb_n    = (n + T - 1) / T;
    int gb_e    = (e + T - 1) / T;
    int gb_gemm = (4 * n + T - 1) / T;              // 1563 (4 threads/row)
    int gb_cnt  = (e / 4 + T - 1) / T;              // 3125 (4 edges/thread)
    int gb_fused = gb_gemm + gb_cnt;
    int gb_2n = (2 * n + T - 1) / T;
    int gb_4e = (int)(((long long)e * 4 + T - 1) / T);

    k_fused     <<<gb_fused, T>>>(x, W1, ei, n, e, gb_gemm);
    k_scale     <<<gb_2n, T>>>(n);
    k_scatter1  <<<gb_4e, T>>>(ei, e);
    k_fin1_gemm2<<<gb_n, T>>>(b1, W2, n);
    k_scatter2  <<<gb_e, T>>>(ei, e);
    k_final     <<<gb_n, T>>>(b2, out, n);
}

// round 14
// speedup vs baseline: 1.4386x; 1.4386x over previous
#include <cuda_runtime.h>
#include <cuda_fp16.h>
#include <stdint.h>

// Problem constants (fixed for GCN_69097433858735)
#define NN 100000
#define EE 3200000
#define FIN 128
#define HH 16
#define CC 2
#define T 256

// Static scratch (zero-initialized at load; g_cnt zero-invariant restored by k_final)
__device__ int   g_cnt [NN];                      // in-degree (edges only)
__device__ float g_dinv[NN];                      // rsqrt(deg+1)
__device__ __align__(16) float  g_h   [NN * HH];  // x@W1 (unscaled)
__device__ __align__(16) __half g_hsh [NN * HH];  // h * dinv[n]  (fp16 scatter payload)
__device__ __align__(16) float  g_acc1[NN * HH];  // seeded with self-loop di*h
__device__ __align__(16) float  g_gs  [NN * CC];  // (relu_out @ W2) * dinv[n]
__device__ __align__(16) float  g_acc2[NN * CC];  // seeded with self-loop gs

__device__ __forceinline__ unsigned h2_bits(__half2 h) {
    return *reinterpret_cast<unsigned*>(&h);
}

// 1) FUSED (sequential split): blocks [0, gemm_blocks) compute h = x@W1
//    (unscaled, 2 threads/row); blocks [gemm_blocks, ...) count in-degrees
//    (4 edges/thread). Count blocks backfill as the gemm wave drains.
__global__ __launch_bounds__(T) void k_fused(const float* __restrict__ x,
                                             const float* __restrict__ W1,
                                             const int* __restrict__ ei,
                                             int n, int e, int gemm_blocks) {
    if ((int)blockIdx.x >= gemm_blocks) {
        // ---- degree count part: int4-vectorized over the dst half ----
        int base = ((blockIdx.x - gemm_blocks) * T + threadIdx.x) * 4;
        if (base >= e) return;
        const int* dstp = ei + e;
        if (base + 3 < e) {
            int4 d4 = *(const int4*)(dstp + base);
            int a = d4.x, b = d4.y, c = d4.z, d = d4.w;
            if ((unsigned)a >= NN) a = 0;
            if ((unsigned)b >= NN) b = 0;
            if ((unsigned)c >= NN) c = 0;
            if ((unsigned)d >= NN) d = 0;
            atomicAdd(&g_cnt[a], 1);
            atomicAdd(&g_cnt[b], 1);
            atomicAdd(&g_cnt[c], 1);
            atomicAdd(&g_cnt[d], 1);
        } else {
            for (int i = base; i < e; i++) {
                int d = dstp[i];
                if ((unsigned)d >= NN) d = 0;
                atomicAdd(&g_cnt[d], 1);
            }
        }
        return;
    }
    // ---- gemm part: 2 threads per row, each covers 64 K-elements ----
    __shared__ float sW1[FIN * HH];  // 8 KB
    for (int i = threadIdx.x; i < FIN * HH; i += T)
        sW1[i] = W1[i];
    __syncthreads();

    int t    = blockIdx.x * T + threadIdx.x;
    int row  = t >> 1;
    int half = t & 1;
    if (row >= n) return;

    float acc[HH];
#pragma unroll
    for (int j = 0; j < HH; j++) acc[j] = 0.0f;

    const float4* xr = (const float4*)(x + (long long)row * FIN) + half * 16;
    const float*  w  = sW1 + half * 64 * HH;
#pragma unroll 8
    for (int k4 = 0; k4 < 16; k4++) {
        float4 xv = __ldg(&xr[k4]);
        int k = k4 * 4;
#pragma unroll
        for (int j = 0; j < HH; j++) {
            acc[j] += xv.x * w[(k + 0) * HH + j];
            acc[j] += xv.y * w[(k + 1) * HH + j];
            acc[j] += xv.z * w[(k + 2) * HH + j];
            acc[j] += xv.w * w[(k + 3) * HH + j];
        }
    }
#pragma unroll
    for (int j = 0; j < HH; j++)
        acc[j] += __shfl_xor_sync(0xffffffffu, acc[j], 1);

    float4* h4 = (float4*)(g_h + (long long)row * HH);
#pragma unroll
    for (int q = 0; q < 2; q++) {
        int qq = half * 2 + q;
        h4[qq] = make_float4(acc[qq * 4 + 0], acc[qq * 4 + 1],
                             acc[qq * 4 + 2], acc[qq * 4 + 3]);
    }
}

// 2) scale: dinv = rsqrt(cnt+1); hsh = fp16(h*dinv); acc1 seeded = di*h
//    (the self-loop message), so fin1 needs neither a zero nor g_h.
__global__ __launch_bounds__(T) void k_scale(int n) {
    int t   = blockIdx.x * T + threadIdx.x;
    int row = t >> 1;
    int hf  = t & 1;
    if (row >= n) return;
    float di = rsqrtf((float)(g_cnt[row] + 1));
    if (hf == 0) g_dinv[row] = di;
    const float4* h4 = (const float4*)(g_h + (long long)row * HH) + hf * 2;
    float4 a = h4[0];
    float4 b = h4[1];
    a.x *= di; a.y *= di; a.z *= di; a.w *= di;
    b.x *= di; b.y *= di; b.z *= di; b.w *= di;
    uint4 packed;
    packed.x = h2_bits(__floats2half2_rn(a.x, a.y));
    packed.y = h2_bits(__floats2half2_rn(a.z, a.w));
    packed.z = h2_bits(__floats2half2_rn(b.x, b.y));
    packed.w = h2_bits(__floats2half2_rn(b.z, b.w));
    *((uint4*)(g_hsh + (long long)row * HH) + hf) = packed;
    float4* a4 = (float4*)(g_acc1 + (long long)row * HH) + hf * 2;
    a4[0] = a;   // self-loop seed (fp32, exact)
    a4[1] = b;
}

// 3) scatter layer 1: acc1[dst] += hs[src] — 4 threads per edge, fp16 gather,
//    fp32 float4 RED (one gather line + one RED line per edge).
__global__ __launch_bounds__(T) void k_scatter1(const int* __restrict__ ei, int e) {
    int gt    = blockIdx.x * T + threadIdx.x;
    int lane  = threadIdx.x & 31;
    int wbase = (gt >> 5) * 8;          // first edge of this warp
    int k = lane >> 2;                  // edge slot within warp (0..7)
    int q = lane & 3;                   // quarter of the 16-feature row

    // coalesced index loads: lanes 0-7 load 8 src, lanes 8-15 load 8 dst
    int idx = wbase + (lane & 7);
    int tmp = 0;
    if (lane < 16 && idx < e)
        tmp = (lane < 8) ? ei[idx] : ei[e + idx];
    int s = __shfl_sync(0xffffffffu, tmp, k);
    int d = __shfl_sync(0xffffffffu, tmp, 8 + k);

    int eb = wbase + k;
    if (eb >= e) return;
    if ((unsigned)s >= NN) s = 0;
    if ((unsigned)d >= NN) d = 0;

    uint2 raw = __ldg((const uint2*)(g_hsh + (long long)s * HH) + q);
    __half2 h0 = *(__half2*)&raw.x;
    __half2 h1 = *(__half2*)&raw.y;
    float2 f0 = __half22float2(h0);
    float2 f1 = __half22float2(h1);
    float4 v = make_float4(f0.x, f0.y, f1.x, f1.y);
    atomicAdd((float4*)(g_acc1 + (long long)d * HH) + q, v);
}

// 4) layer-1 epilogue + GEMM2: out1 = relu(di*acc1 + b1)  (acc1 includes self-loop);
//    gs = (out1 @ W2) * di; acc2 seeded with gs (self-loop)
__global__ __launch_bounds__(T) void k_fin1_gemm2(const float* __restrict__ b1,
                                                  const float* __restrict__ W2,
                                                  int n) {
    __shared__ float sW2[HH * CC];
    __shared__ float sb1[HH];
    for (int i = threadIdx.x; i < HH * CC; i += T) sW2[i] = W2[i];
    for (int i = threadIdx.x; i < HH; i += T) sb1[i] = b1[i];
    __syncthreads();

    int row = blockIdx.x * T + threadIdx.x;
    if (row >= n) return;
    float di = g_dinv[row];

    const float4* ac4 = (const float4*)(g_acc1 + (long long)row * HH);
    float gc0 = 0.f, gc1 = 0.f;
#pragma unroll
    for (int q = 0; q < HH / 4; q++) {
        float4 a = ac4[q];
        float o0 = fmaxf(di * a.x + sb1[q * 4 + 0], 0.f);
        float o1 = fmaxf(di * a.y + sb1[q * 4 + 1], 0.f);
        float o2 = fmaxf(di * a.z + sb1[q * 4 + 2], 0.f);
        float o3 = fmaxf(di * a.w + sb1[q * 4 + 3], 0.f);
        gc0 += o0 * sW2[(q * 4 + 0) * CC + 0] + o1 * sW2[(q * 4 + 1) * CC + 0]
             + o2 * sW2[(q * 4 + 2) * CC + 0] + o3 * sW2[(q * 4 + 3) * CC + 0];
        gc1 += o0 * sW2[(q * 4 + 0) * CC + 1] + o1 * sW2[(q * 4 + 1) * CC + 1]
             + o2 * sW2[(q * 4 + 2) * CC + 1] + o3 * sW2[(q * 4 + 3) * CC + 1];
    }
    float2 g = make_float2(gc0 * di, gc1 * di);
    *(float2*)(g_gs   + (long long)row * CC) = g;
    *(float2*)(g_acc2 + (long long)row * CC) = g;   // self-loop seed
}

// 5) scatter layer 2: acc2[dst] += gs[src]  (float2 atomicAdd)
__global__ __launch_bounds__(T) void k_scatter2(const int* __restrict__ ei, int e) {
    int i = blockIdx.x * T + threadIdx.x;
    if (i >= e) return;
    int s = ei[i];
    int d = ei[e + i];
    if ((unsigned)s >= NN) s = 0;
    if ((unsigned)d >= NN) d = 0;
    float2 v = __ldg((const float2*)(g_gs + (long long)s * CC));
    atomicAdd((float2*)(g_acc2 + (long long)d * CC), v);
}

// 6) final: out = dinv*acc2 + b2 (acc2 includes self-loop); restore g_cnt zeros
__global__ void k_final(const float* __restrict__ b2, float* __restrict__ out, int n) {
    int row = blockIdx.x * blockDim.x + threadIdx.x;
    if (row >= n) return;
    float di = g_dinv[row];
    float2 a = *((const float2*)(g_acc2 + (long long)row * CC));
    float2 o;
    o.x = di * a.x + b2[0];
    o.y = di * a.y + b2[1];
    *((float2*)(out + (long long)row * CC)) = o;
    g_cnt[row] = 0;   // ready for next graph replay
}

extern "C" void kernel_launch(void* const* d_in, const int* in_sizes, int n_in,
                              void* d_out, int out_size) {
    const float* x  = (const float*)d_in[0];
    const int*   ei = (const int*)d_in[1];    // int32 (JAX x64 disabled)
    const float* W1 = (const float*)d_in[2];
    const float* b1 = (const float*)d_in[3];
    const float* W2 = (const float*)d_in[4];
    const float* b2 = (const float*)d_in[5];
    float* out = (float*)d_out;

    int n = in_sizes[0] / FIN;     // 100000
    int e = in_sizes[1] / 2;       // 3200000

    int gb_n    = (n + T - 1) / T;
    int gb_e    = (e + T - 1) / T;
    int gb_gemm = (2 * n + T - 1) / T;              // 782 (2 threads/row)
    int gb_cnt  = (e / 4 + T - 1) / T;              // 3125 (4 edges/thread)
    int gb_fused = gb_gemm + gb_cnt;
    int gb_2n = (2 * n + T - 1) / T;
    int gb_4e = (int)(((long long)e * 4 + T - 1) / T);

    k_fused     <<<gb_fused, T>>>(x, W1, ei, n, e, gb_gemm);
    k_scale     <<<gb_2n, T>>>(n);
    k_scatter1  <<<gb_4e, T>>>(ei, e);
    k_fin1_gemm2<<<gb_n, T>>>(b1, W2, n);
    k_scatter2  <<<gb_e, T>>>(ei, e);
    k_final     <<<gb_n, T>>>(b2, out, n);
}

// round 15
// speedup vs baseline: 1.4796x; 1.0285x over previous
#include <cuda_runtime.h>
#include <cuda_fp16.h>
#include <stdint.h>

// Problem constants (fixed for GCN_69097433858735)
#define NN 100000
#define EE 3200000
#define FIN 128
#define HH 16
#define CC 2
#define T 256

// Static scratch (zero-initialized at load; g_cnt zero-invariant restored by k_final)
__device__ int   g_cnt [NN];                      // in-degree (edges only)
__device__ float g_dinv[NN];                      // rsqrt(deg+1)
__device__ __align__(16) float  g_h   [NN * HH];  // x@W1 (unscaled)
__device__ __align__(16) __half g_hsh [NN * HH];  // h * dinv[n]  (fp16 scatter payload)
__device__ __align__(16) float  g_acc1[NN * HH];  // seeded with self-loop di*h
__device__ __align__(16) float  g_gs  [NN * CC];  // (relu_out @ W2) * dinv[n]
__device__ __align__(16) float  g_acc2[NN * CC];  // seeded with self-loop gs

__device__ __forceinline__ unsigned h2_bits(__half2 h) {
    return *reinterpret_cast<unsigned*>(&h);
}

// 1) FUSED (sequential split): blocks [0, gemm_blocks) compute h = x@W1
//    (unscaled, 2 threads/row); blocks [gemm_blocks, ...) count in-degrees
//    (4 edges/thread). Count blocks backfill as the gemm wave drains.
__global__ __launch_bounds__(T) void k_fused(const float* __restrict__ x,
                                             const float* __restrict__ W1,
                                             const int* __restrict__ ei,
                                             int n, int e, int gemm_blocks) {
    if ((int)blockIdx.x >= gemm_blocks) {
        // ---- degree count part: int4-vectorized over the dst half ----
        int base = ((blockIdx.x - gemm_blocks) * T + threadIdx.x) * 4;
        if (base >= e) return;
        const int* dstp = ei + e;
        if (base + 3 < e) {
            int4 d4 = *(const int4*)(dstp + base);
            int a = d4.x, b = d4.y, c = d4.z, d = d4.w;
            if ((unsigned)a >= NN) a = 0;
            if ((unsigned)b >= NN) b = 0;
            if ((unsigned)c >= NN) c = 0;
            if ((unsigned)d >= NN) d = 0;
            atomicAdd(&g_cnt[a], 1);
            atomicAdd(&g_cnt[b], 1);
            atomicAdd(&g_cnt[c], 1);
            atomicAdd(&g_cnt[d], 1);
        } else {
            for (int i = base; i < e; i++) {
                int d = dstp[i];
                if ((unsigned)d >= NN) d = 0;
                atomicAdd(&g_cnt[d], 1);
            }
        }
        return;
    }
    // ---- gemm part: 2 threads per row, each covers 64 K-elements ----
    __shared__ float sW1[FIN * HH];  // 8 KB
    for (int i = threadIdx.x; i < FIN * HH; i += T)
        sW1[i] = W1[i];
    __syncthreads();

    int t    = blockIdx.x * T + threadIdx.x;
    int row  = t >> 1;
    int half = t & 1;
    if (row >= n) return;

    float acc[HH];
#pragma unroll
    for (int j = 0; j < HH; j++) acc[j] = 0.0f;

    const float4* xr = (const float4*)(x + (long long)row * FIN) + half * 16;
    const float*  w  = sW1 + half * 64 * HH;
#pragma unroll 8
    for (int k4 = 0; k4 < 16; k4++) {
        float4 xv = __ldg(&xr[k4]);
        int k = k4 * 4;
#pragma unroll
        for (int j = 0; j < HH; j++) {
            acc[j] += xv.x * w[(k + 0) * HH + j];
            acc[j] += xv.y * w[(k + 1) * HH + j];
            acc[j] += xv.z * w[(k + 2) * HH + j];
            acc[j] += xv.w * w[(k + 3) * HH + j];
        }
    }
#pragma unroll
    for (int j = 0; j < HH; j++)
        acc[j] += __shfl_xor_sync(0xffffffffu, acc[j], 1);

    float4* h4 = (float4*)(g_h + (long long)row * HH);
#pragma unroll
    for (int q = 0; q < 2; q++) {
        int qq = half * 2 + q;
        h4[qq] = make_float4(acc[qq * 4 + 0], acc[qq * 4 + 1],
                             acc[qq * 4 + 2], acc[qq * 4 + 3]);
    }
}

// 2) scale: dinv = rsqrt(cnt+1); hsh = fp16(h*dinv); acc1 seeded = di*h
//    (the self-loop message), so fin1 needs neither a zero nor g_h.
__global__ __launch_bounds__(T) void k_scale(int n) {
    int t   = blockIdx.x * T + threadIdx.x;
    int row = t >> 1;
    int hf  = t & 1;
    if (row >= n) return;
    float di = rsqrtf((float)(g_cnt[row] + 1));
    if (hf == 0) g_dinv[row] = di;
    const float4* h4 = (const float4*)(g_h + (long long)row * HH) + hf * 2;
    float4 a = h4[0];
    float4 b = h4[1];
    a.x *= di; a.y *= di; a.z *= di; a.w *= di;
    b.x *= di; b.y *= di; b.z *= di; b.w *= di;
    uint4 packed;
    packed.x = h2_bits(__floats2half2_rn(a.x, a.y));
    packed.y = h2_bits(__floats2half2_rn(a.z, a.w));
    packed.z = h2_bits(__floats2half2_rn(b.x, b.y));
    packed.w = h2_bits(__floats2half2_rn(b.z, b.w));
    *((uint4*)(g_hsh + (long long)row * HH) + hf) = packed;
    float4* a4 = (float4*)(g_acc1 + (long long)row * HH) + hf * 2;
    a4[0] = a;   // self-loop seed (fp32, exact)
    a4[1] = b;
}

// 3) scatter layer 1: acc1[dst] += hs[src] — 4 lanes per edge, 2 EDGES PER THREAD
//    (16 edges/warp). fp16 gather, fp32 float4 RED; two independent
//    gather->RED chains per thread double the MLP behind the L2 latency.
__global__ __launch_bounds__(T) void k_scatter1(const int* __restrict__ ei, int e) {
    int gt    = blockIdx.x * T + threadIdx.x;
    int lane  = threadIdx.x & 31;
    int wbase = (gt >> 5) * 16;         // first edge of this warp (16 edges)
    int k = lane >> 2;                  // edge slot within half-batch (0..7)
    int q = lane & 3;                   // quarter of the 16-float row

    // coalesced index loads: lanes 0-15 -> 16 src, lanes 16-31 -> 16 dst
    int idx = wbase + (lane & 15);
    int tmp = 0;
    if (idx < e)
        tmp = (lane < 16) ? ei[idx] : ei[e + idx];
    int s0 = __shfl_sync(0xffffffffu, tmp, k);
    int s1 = __shfl_sync(0xffffffffu, tmp, 8 + k);
    int d0 = __shfl_sync(0xffffffffu, tmp, 16 + k);
    int d1 = __shfl_sync(0xffffffffu, tmp, 24 + k);

    bool p0 = (wbase + k) < e;
    bool p1 = (wbase + 8 + k) < e;
    if ((unsigned)s0 >= NN) s0 = 0;
    if ((unsigned)d0 >= NN) d0 = 0;
    if ((unsigned)s1 >= NN) s1 = 0;
    if ((unsigned)d1 >= NN) d1 = 0;

    uint2 raw0 = make_uint2(0u, 0u), raw1 = make_uint2(0u, 0u);
    if (p0) raw0 = __ldg((const uint2*)(g_hsh + (long long)s0 * HH) + q);
    if (p1) raw1 = __ldg((const uint2*)(g_hsh + (long long)s1 * HH) + q);

    if (p0) {
        float2 f0 = __half22float2(*(__half2*)&raw0.x);
        float2 f1 = __half22float2(*(__half2*)&raw0.y);
        atomicAdd((float4*)(g_acc1 + (long long)d0 * HH) + q,
                  make_float4(f0.x, f0.y, f1.x, f1.y));
    }
    if (p1) {
        float2 f0 = __half22float2(*(__half2*)&raw1.x);
        float2 f1 = __half22float2(*(__half2*)&raw1.y);
        atomicAdd((float4*)(g_acc1 + (long long)d1 * HH) + q,
                  make_float4(f0.x, f0.y, f1.x, f1.y));
    }
}

// 4) layer-1 epilogue + GEMM2: out1 = relu(di*acc1 + b1)  (acc1 includes self-loop);
//    gs = (out1 @ W2) * di; acc2 seeded with gs (self-loop)
__global__ __launch_bounds__(T) void k_fin1_gemm2(const float* __restrict__ b1,
                                                  const float* __restrict__ W2,
                                                  int n) {
    __shared__ float sW2[HH * CC];
    __shared__ float sb1[HH];
    for (int i = threadIdx.x; i < HH * CC; i += T) sW2[i] = W2[i];
    for (int i = threadIdx.x; i < HH; i += T) sb1[i] = b1[i];
    __syncthreads();

    int row = blockIdx.x * T + threadIdx.x;
    if (row >= n) return;
    float di = g_dinv[row];

    const float4* ac4 = (const float4*)(g_acc1 + (long long)row * HH);
    float gc0 = 0.f, gc1 = 0.f;
#pragma unroll
    for (int q = 0; q < HH / 4; q++) {
        float4 a = ac4[q];
        float o0 = fmaxf(di * a.x + sb1[q * 4 + 0], 0.f);
        float o1 = fmaxf(di * a.y + sb1[q * 4 + 1], 0.f);
        float o2 = fmaxf(di * a.z + sb1[q * 4 + 2], 0.f);
        float o3 = fmaxf(di * a.w + sb1[q * 4 + 3], 0.f);
        gc0 += o0 * sW2[(q * 4 + 0) * CC + 0] + o1 * sW2[(q * 4 + 1) * CC + 0]
             + o2 * sW2[(q * 4 + 2) * CC + 0] + o3 * sW2[(q * 4 + 3) * CC + 0];
        gc1 += o0 * sW2[(q * 4 + 0) * CC + 1] + o1 * sW2[(q * 4 + 1) * CC + 1]
             + o2 * sW2[(q * 4 + 2) * CC + 1] + o3 * sW2[(q * 4 + 3) * CC + 1];
    }
    float2 g = make_float2(gc0 * di, gc1 * di);
    *(float2*)(g_gs   + (long long)row * CC) = g;
    *(float2*)(g_acc2 + (long long)row * CC) = g;   // self-loop seed
}

// 5) scatter layer 2: acc2[dst] += gs[src] — 2 EDGES PER THREAD (int2 index
//    loads, two independent gather->RED chains).
__global__ __launch_bounds__(T) void k_scatter2(const int* __restrict__ ei, int e) {
    int i = (blockIdx.x * T + threadIdx.x) * 2;
    if (i >= e) return;
    if (i + 1 < e) {
        int2 s2 = *(const int2*)(ei + i);
        int2 d2 = *(const int2*)(ei + e + i);
        int s0 = s2.x, s1 = s2.y, d0 = d2.x, d1 = d2.y;
        if ((unsigned)s0 >= NN) s0 = 0;
        if ((unsigned)s1 >= NN) s1 = 0;
        if ((unsigned)d0 >= NN) d0 = 0;
        if ((unsigned)d1 >= NN) d1 = 0;
        float2 v0 = __ldg((const float2*)(g_gs + (long long)s0 * CC));
        float2 v1 = __ldg((const float2*)(g_gs + (long long)s1 * CC));
        atomicAdd((float2*)(g_acc2 + (long long)d0 * CC), v0);
        atomicAdd((float2*)(g_acc2 + (long long)d1 * CC), v1);
    } else {
        int s = ei[i];
        int d = ei[e + i];
        if ((unsigned)s >= NN) s = 0;
        if ((unsigned)d >= NN) d = 0;
        float2 v = __ldg((const float2*)(g_gs + (long long)s * CC));
        atomicAdd((float2*)(g_acc2 + (long long)d * CC), v);
    }
}

// 6) final: out = dinv*acc2 + b2 (acc2 includes self-loop); restore g_cnt zeros
__global__ void k_final(const float* __restrict__ b2, float* __restrict__ out, int n) {
    int row = blockIdx.x * blockDim.x + threadIdx.x;
    if (row >= n) return;
    float di = g_dinv[row];
    float2 a = *((const float2*)(g_acc2 + (long long)row * CC));
    float2 o;
    o.x = di * a.x + b2[0];
    o.y = di * a.y + b2[1];
    *((float2*)(out + (long long)row * CC)) = o;
    g_cnt[row] = 0;   // ready for next graph replay
}

extern "C" void kernel_launch(void* const* d_in, const int* in_sizes, int n_in,
                              void* d_out, int out_size) {
    const float* x  = (const float*)d_in[0];
    const int*   ei = (const int*)d_in[1];    // int32 (JAX x64 disabled)
    const float* W1 = (const float*)d_in[2];
    const float* b1 = (const float*)d_in[3];
    const float* W2 = (const float*)d_in[4];
    const float* b2 = (const float*)d_in[5];
    float* out = (float*)d_out;

    int n = in_sizes[0] / FIN;     // 100000
    int e = in_sizes[1] / 2;       // 3200000

    int gb_n    = (n + T - 1) / T;
    int gb_gemm = (2 * n + T - 1) / T;              // 782 (2 threads/row)
    int gb_cnt  = (e / 4 + T - 1) / T;              // 3125 (4 edges/thread)
    int gb_fused = gb_gemm + gb_cnt;
    int gb_2n = (2 * n + T - 1) / T;
    int gb_s1 = (int)(((long long)e * 2 + T - 1) / T);   // 2 edges/thread, 4 lanes/edge
    int gb_s2 = (e / 2 + T - 1) / T;                     // 2 edges/thread

    k_fused     <<<gb_fused, T>>>(x, W1, ei, n, e, gb_gemm);
    k_scale     <<<gb_2n, T>>>(n);
    k_scatter1  <<<gb_s1, T>>>(ei, e);
    k_fin1_gemm2<<<gb_n, T>>>(b1, W2, n);
    k_scatter2  <<<gb_s2, T>>>(ei, e);
    k_final     <<<gb_n, T>>>(b2, out, n);
}

// round 16
// speedup vs baseline: 1.4799x; 1.0002x over previous
#include <cuda_runtime.h>
#include <cuda_fp16.h>
#include <stdint.h>

// Problem constants (fixed for GCN_69097433858735)
#define NN 100000
#define EE 3200000
#define FIN 128
#define HH 16
#define CC 2
#define T 256

// Static scratch (zero-initialized at load; g_cnt zero-invariant restored by k_final)
__device__ int   g_cnt [NN];                      // in-degree (edges only)
__device__ float g_dinv[NN];                      // rsqrt(deg+1)
__device__ __align__(16) float  g_h   [NN * HH];  // x@W1 (unscaled)
__device__ __align__(16) __half g_hsh [NN * HH];  // h * dinv[n]  (fp16 scatter payload)
__device__ __align__(16) float  g_acc1[NN * HH];  // seeded with self-loop di*h
__device__ __align__(16) float  g_gs  [NN * CC];  // (relu_out @ W2) * dinv[n]
__device__ __align__(16) float  g_acc2[NN * CC];  // seeded with self-loop gs

__device__ __forceinline__ unsigned h2_bits(__half2 h) {
    return *reinterpret_cast<unsigned*>(&h);
}

// 1) FUSED (sequential split): blocks [0, gemm_blocks) compute h = x@W1
//    (unscaled, 2 threads/row); blocks [gemm_blocks, ...) count in-degrees
//    (4 edges/thread). Count blocks backfill as the gemm wave drains.
__global__ __launch_bounds__(T) void k_fused(const float* __restrict__ x,
                                             const float* __restrict__ W1,
                                             const int* __restrict__ ei,
                                             int n, int e, int gemm_blocks) {
    if ((int)blockIdx.x >= gemm_blocks) {
        // ---- degree count part: int4-vectorized over the dst half ----
        int base = ((blockIdx.x - gemm_blocks) * T + threadIdx.x) * 4;
        if (base >= e) return;
        const int* dstp = ei + e;
        if (base + 3 < e) {
            int4 d4 = *(const int4*)(dstp + base);
            int a = d4.x, b = d4.y, c = d4.z, d = d4.w;
            if ((unsigned)a >= NN) a = 0;
            if ((unsigned)b >= NN) b = 0;
            if ((unsigned)c >= NN) c = 0;
            if ((unsigned)d >= NN) d = 0;
            atomicAdd(&g_cnt[a], 1);
            atomicAdd(&g_cnt[b], 1);
            atomicAdd(&g_cnt[c], 1);
            atomicAdd(&g_cnt[d], 1);
        } else {
            for (int i = base; i < e; i++) {
                int d = dstp[i];
                if ((unsigned)d >= NN) d = 0;
                atomicAdd(&g_cnt[d], 1);
            }
        }
        return;
    }
    // ---- gemm part: 2 threads per row, each covers 64 K-elements ----
    __shared__ float sW1[FIN * HH];  // 8 KB
    for (int i = threadIdx.x; i < FIN * HH; i += T)
        sW1[i] = W1[i];
    __syncthreads();

    int t    = blockIdx.x * T + threadIdx.x;
    int row  = t >> 1;
    int half = t & 1;
    if (row >= n) return;

    float acc[HH];
#pragma unroll
    for (int j = 0; j < HH; j++) acc[j] = 0.0f;

    const float4* xr = (const float4*)(x + (long long)row * FIN) + half * 16;
    const float*  w  = sW1 + half * 64 * HH;
#pragma unroll 8
    for (int k4 = 0; k4 < 16; k4++) {
        float4 xv = __ldg(&xr[k4]);
        int k = k4 * 4;
#pragma unroll
        for (int j = 0; j < HH; j++) {
            acc[j] += xv.x * w[(k + 0) * HH + j];
            acc[j] += xv.y * w[(k + 1) * HH + j];
            acc[j] += xv.z * w[(k + 2) * HH + j];
            acc[j] += xv.w * w[(k + 3) * HH + j];
        }
    }
#pragma unroll
    for (int j = 0; j < HH; j++)
        acc[j] += __shfl_xor_sync(0xffffffffu, acc[j], 1);

    float4* h4 = (float4*)(g_h + (long long)row * HH);
#pragma unroll
    for (int q = 0; q < 2; q++) {
        int qq = half * 2 + q;
        h4[qq] = make_float4(acc[qq * 4 + 0], acc[qq * 4 + 1],
                             acc[qq * 4 + 2], acc[qq * 4 + 3]);
    }
}

// 2) scale: dinv = rsqrt(cnt+1); hsh = fp16(h*dinv); acc1 seeded = di*h
//    (the self-loop message), so fin1 needs neither a zero nor g_h.
__global__ __launch_bounds__(T) void k_scale(int n) {
    int t   = blockIdx.x * T + threadIdx.x;
    int row = t >> 1;
    int hf  = t & 1;
    if (row >= n) return;
    float di = rsqrtf((float)(g_cnt[row] + 1));
    if (hf == 0) g_dinv[row] = di;
    const float4* h4 = (const float4*)(g_h + (long long)row * HH) + hf * 2;
    float4 a = h4[0];
    float4 b = h4[1];
    a.x *= di; a.y *= di; a.z *= di; a.w *= di;
    b.x *= di; b.y *= di; b.z *= di; b.w *= di;
    uint4 packed;
    packed.x = h2_bits(__floats2half2_rn(a.x, a.y));
    packed.y = h2_bits(__floats2half2_rn(a.z, a.w));
    packed.z = h2_bits(__floats2half2_rn(b.x, b.y));
    packed.w = h2_bits(__floats2half2_rn(b.z, b.w));
    *((uint4*)(g_hsh + (long long)row * HH) + hf) = packed;
    float4* a4 = (float4*)(g_acc1 + (long long)row * HH) + hf * 2;
    a4[0] = a;   // self-loop seed (fp32, exact)
    a4[1] = b;
}

// 3) scatter layer 1: acc1[dst] += hs[src] — 4 lanes per edge, 4 EDGES PER
//    THREAD (32 edges/warp). All 32 lanes load src+dst coalesced; each thread
//    runs 4 independent fp16-gather -> fp32-float4-RED chains.
__global__ __launch_bounds__(T) void k_scatter1(const int* __restrict__ ei, int e) {
    int gt    = blockIdx.x * T + threadIdx.x;
    int lane  = threadIdx.x & 31;
    int wbase = (gt >> 5) * 32;         // first edge of this warp (32 edges)
    int k = lane >> 2;                  // edge slot within batch-of-8 (0..7)
    int q = lane & 3;                   // quarter of the 16-float row

    // coalesced index loads: every lane loads one src + one dst
    int idx = wbase + lane;
    int tS = 0, tD = 0;
    if (idx < e) {
        tS = ei[idx];
        tD = ei[e + idx];
    }

    float4* accbase = (float4*)g_acc1;
#pragma unroll
    for (int j = 0; j < 4; j++) {
        int slot = k + j * 8;
        if (wbase + slot >= e) break;
        int s = __shfl_sync(0xffffffffu, tS, slot);
        int d = __shfl_sync(0xffffffffu, tD, slot);
        if ((unsigned)s >= NN) s = 0;
        if ((unsigned)d >= NN) d = 0;
        uint2 raw = __ldg((const uint2*)(g_hsh + (long long)s * HH) + q);
        float2 f0 = __half22float2(*(__half2*)&raw.x);
        float2 f1 = __half22float2(*(__half2*)&raw.y);
        atomicAdd(accbase + (long long)d * 4 + q,
                  make_float4(f0.x, f0.y, f1.x, f1.y));
    }
}

// 4) layer-1 epilogue + GEMM2: out1 = relu(di*acc1 + b1)  (acc1 includes self-loop);
//    gs = (out1 @ W2) * di; acc2 seeded with gs (self-loop)
__global__ __launch_bounds__(T) void k_fin1_gemm2(const float* __restrict__ b1,
                                                  const float* __restrict__ W2,
                                                  int n) {
    __shared__ float sW2[HH * CC];
    __shared__ float sb1[HH];
    for (int i = threadIdx.x; i < HH * CC; i += T) sW2[i] = W2[i];
    for (int i = threadIdx.x; i < HH; i += T) sb1[i] = b1[i];
    __syncthreads();

    int row = blockIdx.x * T + threadIdx.x;
    if (row >= n) return;
    float di = g_dinv[row];

    const float4* ac4 = (const float4*)(g_acc1 + (long long)row * HH);
    float gc0 = 0.f, gc1 = 0.f;
#pragma unroll
    for (int q = 0; q < HH / 4; q++) {
        float4 a = ac4[q];
        float o0 = fmaxf(di * a.x + sb1[q * 4 + 0], 0.f);
        float o1 = fmaxf(di * a.y + sb1[q * 4 + 1], 0.f);
        float o2 = fmaxf(di * a.z + sb1[q * 4 + 2], 0.f);
        float o3 = fmaxf(di * a.w + sb1[q * 4 + 3], 0.f);
        gc0 += o0 * sW2[(q * 4 + 0) * CC + 0] + o1 * sW2[(q * 4 + 1) * CC + 0]
             + o2 * sW2[(q * 4 + 2) * CC + 0] + o3 * sW2[(q * 4 + 3) * CC + 0];
        gc1 += o0 * sW2[(q * 4 + 0) * CC + 1] + o1 * sW2[(q * 4 + 1) * CC + 1]
             + o2 * sW2[(q * 4 + 2) * CC + 1] + o3 * sW2[(q * 4 + 3) * CC + 1];
    }
    float2 g = make_float2(gc0 * di, gc1 * di);
    *(float2*)(g_gs   + (long long)row * CC) = g;
    *(float2*)(g_acc2 + (long long)row * CC) = g;   // self-loop seed
}

// 5) scatter layer 2: acc2[dst] += gs[src] — 4 EDGES PER THREAD (int4 index
//    loads, four independent gather->RED chains).
__global__ __launch_bounds__(T) void k_scatter2(const int* __restrict__ ei, int e) {
    int i = (blockIdx.x * T + threadIdx.x) * 4;
    if (i >= e) return;
    if (i + 3 < e) {
        int4 s4 = *(const int4*)(ei + i);
        int4 d4 = *(const int4*)(ei + e + i);
        int s0 = s4.x, s1 = s4.y, s2 = s4.z, s3 = s4.w;
        int d0 = d4.x, d1 = d4.y, d2 = d4.z, d3 = d4.w;
        if ((unsigned)s0 >= NN) s0 = 0;
        if ((unsigned)s1 >= NN) s1 = 0;
        if ((unsigned)s2 >= NN) s2 = 0;
        if ((unsigned)s3 >= NN) s3 = 0;
        if ((unsigned)d0 >= NN) d0 = 0;
        if ((unsigned)d1 >= NN) d1 = 0;
        if ((unsigned)d2 >= NN) d2 = 0;
        if ((unsigned)d3 >= NN) d3 = 0;
        float2 v0 = __ldg((const float2*)(g_gs + (long long)s0 * CC));
        float2 v1 = __ldg((const float2*)(g_gs + (long long)s1 * CC));
        float2 v2 = __ldg((const float2*)(g_gs + (long long)s2 * CC));
        float2 v3 = __ldg((const float2*)(g_gs + (long long)s3 * CC));
        atomicAdd((float2*)(g_acc2 + (long long)d0 * CC), v0);
        atomicAdd((float2*)(g_acc2 + (long long)d1 * CC), v1);
        atomicAdd((float2*)(g_acc2 + (long long)d2 * CC), v2);
        atomicAdd((float2*)(g_acc2 + (long long)d3 * CC), v3);
    } else {
        for (; i < e; i++) {
            int s = ei[i];
            int d = ei[e + i];
            if ((unsigned)s >= NN) s = 0;
            if ((unsigned)d >= NN) d = 0;
            float2 v = __ldg((const float2*)(g_gs + (long long)s * CC));
            atomicAdd((float2*)(g_acc2 + (long long)d * CC), v);
        }
    }
}

// 6) final: out = dinv*acc2 + b2 (acc2 includes self-loop); restore g_cnt zeros
__global__ void k_final(const float* __restrict__ b2, float* __restrict__ out, int n) {
    int row = blockIdx.x * blockDim.x + threadIdx.x;
    if (row >= n) return;
    float di = g_dinv[row];
    float2 a = *((const float2*)(g_acc2 + (long long)row * CC));
    float2 o;
    o.x = di * a.x + b2[0];
    o.y = di * a.y + b2[1];
    *((float2*)(out + (long long)row * CC)) = o;
    g_cnt[row] = 0;   // ready for next graph replay
}

extern "C" void kernel_launch(void* const* d_in, const int* in_sizes, int n_in,
                              void* d_out, int out_size) {
    const float* x  = (const float*)d_in[0];
    const int*   ei = (const int*)d_in[1];    // int32 (JAX x64 disabled)
    const float* W1 = (const float*)d_in[2];
    const float* b1 = (const float*)d_in[3];
    const float* W2 = (const float*)d_in[4];
    const float* b2 = (const float*)d_in[5];
    float* out = (float*)d_out;

    int n = in_sizes[0] / FIN;     // 100000
    int e = in_sizes[1] / 2;       // 3200000

    int gb_n    = (n + T - 1) / T;
    int gb_gemm = (2 * n + T - 1) / T;              // 782 (2 threads/row)
    int gb_cnt  = (e / 4 + T - 1) / T;              // 3125 (4 edges/thread)
    int gb_fused = gb_gemm + gb_cnt;
    int gb_2n = (2 * n + T - 1) / T;
    int gb_s1 = (int)(((long long)e + T - 1) / T);  // 4 edges/thread, 4 lanes/edge
    int gb_s2 = (e / 4 + T - 1) / T;                // 4 edges/thread

    k_fused     <<<gb_fused, T>>>(x, W1, ei, n, e, gb_gemm);
    k_scale     <<<gb_2n, T>>>(n);
    k_scatter1  <<<gb_s1, T>>>(ei, e);
    k_fin1_gemm2<<<gb_n, T>>>(b1, W2, n);
    k_scatter2  <<<gb_s2, T>>>(ei, e);
    k_final     <<<gb_n, T>>>(b2, out, n);
}